// round 15
// baseline (speedup 1.0000x reference)
#include <cuda_runtime.h>
#include <cuda_bf16.h>

// pred (16,54,192,192) f32, target (16,6,192,192) f32, loc unused.
// loss = [ bce_sum(pred[:,0:18:2], target[:,0:1]) +
//          bce_sum(pred[:,1:18:2], target[:,1:2]) ] / 9
// Per element: max(x,0) - x*t + log1p(exp(-|x|)).
// Factoring per (pixel, parity): sum_c softplus(x_c) - t * sum_c x_c
// -> target loaded ONCE per (pixel,parity); pred loaded once. ~52 MB L2.
// log trick: sum_i log1p(e_i) = ln( prod4 (1+e_i) ) -> one LG2 per float4.
//
// Schedule: block = (batch, parity, pixel-chunk); TPB=128, 2304 blocks ->
// ~16 CTAs/SM resident (64 warps) with regs capped at 32.

namespace {
constexpr int B        = 16;
constexpr int HW4      = 192 * 192 / 4;      // 9216 float4 per channel slice
constexpr int NPAIR    = 9;                  // channels per parity
constexpr int PRED_CH  = 54;
constexpr int TGT_CH   = 6;

constexpr int TPB      = 128;
constexpr int CHUNKS   = HW4 / TPB;          // 72 pixel chunks per (b,parity)
constexpr int NBLOCKS  = B * 2 * CHUNKS;     // 2304
}

__device__ float        g_partials[NBLOCKS];
__device__ unsigned int g_count = 0;

__device__ __forceinline__ float block_reduce(float acc) {
    #pragma unroll
    for (int o = 16; o > 0; o >>= 1)
        acc += __shfl_xor_sync(0xffffffffu, acc, o);
    __shared__ float s[TPB / 32];
    if ((threadIdx.x & 31) == 0) s[threadIdx.x >> 5] = acc;
    __syncthreads();
    float v = 0.0f;
    if (threadIdx.x < 32) {
        v = (threadIdx.x < TPB / 32) ? s[threadIdx.x] : 0.0f;
        #pragma unroll
        for (int o = 2; o > 0; o >>= 1)
            v += __shfl_xor_sync(0xffffffffu, v, o);
    }
    return v;  // valid in thread 0
}

__global__ __launch_bounds__(TPB, 16)   // 32 regs -> 16 CTAs/SM
void rpn_bce_fused(const float4* __restrict__ pred,
                   const float4* __restrict__ target,
                   float* __restrict__ out) {
    const int tid    = threadIdx.x;
    const int bid    = blockIdx.x;               // 0..2303
    const int chunk  = bid % CHUNKS;             // 0..71
    const int bp     = bid / CHUNKS;             // 0..31
    const int parity = bp & 1;
    const int b      = bp >> 1;

    const int pix = chunk * TPB + tid;           // float4 pixel index

    // channel (parity + 2c) at p + c*2*HW4
    const float4* __restrict__ p =
        pred + ((size_t)b * PRED_CH + parity) * HW4 + pix;

    constexpr float NL2E = -1.44269504088896341f;  // -log2(e)

    float  acc  = 0.0f;                           // sum max(x,0)
    float  lacc = 0.0f;                           // sum log2(prod4(1+e))
    float4 xs   = make_float4(0.f, 0.f, 0.f, 0.f);  // sum x (per component)

    #pragma unroll
    for (int c = 0; c < NPAIR; ++c) {
        const float4 x = __ldg(p + (size_t)c * (2 * HW4));

        const float e0 = exp2f(fabsf(x.x) * NL2E);
        const float e1 = exp2f(fabsf(x.y) * NL2E);
        const float e2 = exp2f(fabsf(x.z) * NL2E);
        const float e3 = exp2f(fabsf(x.w) * NL2E);

        float pr = 1.0f + e0;                     // prod4 (1+e_i) in (1,16]
        pr = fmaf(pr, e1, pr);
        pr = fmaf(pr, e2, pr);
        pr = fmaf(pr, e3, pr);
        lacc += __log2f(pr);                      // one LG2 per 4 elements

        acc += fmaxf(x.x, 0.0f) + fmaxf(x.y, 0.0f)
             + fmaxf(x.z, 0.0f) + fmaxf(x.w, 0.0f);

        xs.x += x.x; xs.y += x.y; xs.z += x.z; xs.w += x.w;
    }

    // Target loaded once per (pixel, parity), after the mainloop.
    const float4 t =
        __ldg(target + ((size_t)b * TGT_CH + parity) * HW4 + pix);

    acc = fmaf(-t.x, xs.x, acc);
    acc = fmaf(-t.y, xs.y, acc);
    acc = fmaf(-t.z, xs.z, acc);
    acc = fmaf(-t.w, xs.w, acc);
    acc = fmaf(0.693147180559945f, lacc, acc);

    const float v = block_reduce(acc);

    // Last-block-done deterministic finalize.
    __shared__ bool s_last;
    if (tid == 0) {
        g_partials[bid] = v;
        __threadfence();
        unsigned int n = atomicAdd(&g_count, 1u);
        s_last = (n == (unsigned int)(NBLOCKS - 1));
    }
    __syncthreads();

    if (s_last) {
        __threadfence();
        float a = 0.0f;
        #pragma unroll
        for (int i = tid; i < NBLOCKS; i += TPB)
            a += g_partials[i];
        const float total = block_reduce(a);
        if (tid == 0) {
            out[0] = total * (1.0f / 9.0f);   // / NUM_OBJ_CLS
            g_count = 0;                      // reset for graph replays
        }
    }
}

extern "C" void kernel_launch(void* const* d_in, const int* in_sizes, int n_in,
                              void* d_out, int out_size) {
    (void)in_sizes; (void)n_in; (void)out_size;
    const float4* pred   = (const float4*)d_in[0];
    const float4* target = (const float4*)d_in[1];
    float* out = (float*)d_out;

    rpn_bce_fused<<<NBLOCKS, TPB>>>(pred, target, out);
}

// round 17
// speedup vs baseline: 1.6290x; 1.6290x over previous
#include <cuda_runtime.h>
#include <cuda_bf16.h>

// pred (16,54,192,192) f32, target (16,6,192,192) f32, loc unused.
// loss = [ bce_sum(pred[:,0:18:2], target[:,0:1]) +
//          bce_sum(pred[:,1:18:2], target[:,1:2]) ] / 9
// Per element: max(x,0) - x*t + log1p(exp(-|x|)).
// Factoring per pixel: sum_c softplus(x_c) - t0*sum x_even - t1*sum x_odd
// -> target loaded ONCE per pixel (47 MB total traffic).
// log trick: sum_i log1p(e_i) = ln( prod8 (1+e_i) ), e in (0,1] ->
// prod8 in (1,256] exact in f32 -> one LG2 per 8 elements.
//
// Schedule: block = (batch, pixel-chunk); TPB=128, 1152 blocks -> 7.8 CTAs/SM
// (GRID-limited occupancy). Register budget deliberately opened up
// (launch_bounds min-blocks=6 -> ~85 regs) so the 18 independent channel
// loads can be software-pipelined: registers are free here, warps are not.

namespace {
constexpr int B        = 16;
constexpr int HW4      = 192 * 192 / 4;      // 9216 float4 per channel slice
constexpr int NPAIR    = 9;
constexpr int PRED_CH  = 54;
constexpr int TGT_CH   = 6;

constexpr int TPB      = 128;
constexpr int CHUNKS   = HW4 / TPB;          // 72 pixel chunks per batch
constexpr int NBLOCKS  = B * CHUNKS;         // 1152
}

__device__ float        g_partials[NBLOCKS];
__device__ unsigned int g_count = 0;

__device__ __forceinline__ float block_reduce(float acc) {
    #pragma unroll
    for (int o = 16; o > 0; o >>= 1)
        acc += __shfl_xor_sync(0xffffffffu, acc, o);
    __shared__ float s[TPB / 32];
    if ((threadIdx.x & 31) == 0) s[threadIdx.x >> 5] = acc;
    __syncthreads();
    float v = 0.0f;
    if (threadIdx.x < 32) {
        v = (threadIdx.x < TPB / 32) ? s[threadIdx.x] : 0.0f;
        #pragma unroll
        for (int o = 2; o > 0; o >>= 1)
            v += __shfl_xor_sync(0xffffffffu, v, o);
    }
    return v;  // valid in thread 0
}

__global__ __launch_bounds__(TPB, 6)   // ~85-reg budget; occupancy is grid-limited
void rpn_bce_fused(const float4* __restrict__ pred,
                   const float4* __restrict__ target,
                   float* __restrict__ out) {
    const int tid   = threadIdx.x;
    const int bid   = blockIdx.x;                // 0..1151
    const int chunk = bid % CHUNKS;              // 0..71
    const int b     = bid / CHUNKS;              // 0..15

    const int pix = chunk * TPB + tid;           // float4 pixel index

    const float4* __restrict__ p =
        pred + (size_t)b * PRED_CH * HW4 + pix;  // channel c at + c*HW4

    constexpr float NL2E = -1.44269504088896341f;  // -log2(e)

    float  acc  = 0.0f;                             // sum max(x,0)
    float  lacc = 0.0f;                             // sum log2(prod8(1+e))
    float4 xs0  = make_float4(0.f, 0.f, 0.f, 0.f);  // sum x, even channels
    float4 xs1  = make_float4(0.f, 0.f, 0.f, 0.f);  // sum x, odd channels

    // 2-deep software pipeline over the 9 channel pairs.
    float4 x0 = __ldg(p + 0 * HW4);
    float4 x1 = __ldg(p + 1 * HW4);

    #pragma unroll
    for (int c = 0; c < NPAIR; ++c) {
        float4 n0, n1;
        if (c + 1 < NPAIR) {                        // preload next pair
            n0 = __ldg(p + (size_t)(2 * c + 2) * HW4);
            n1 = __ldg(p + (size_t)(2 * c + 3) * HW4);
        }

        const float ea = exp2f(fabsf(x0.x) * NL2E);
        const float eb = exp2f(fabsf(x0.y) * NL2E);
        const float ec = exp2f(fabsf(x0.z) * NL2E);
        const float ed = exp2f(fabsf(x0.w) * NL2E);
        const float ee = exp2f(fabsf(x1.x) * NL2E);
        const float ef = exp2f(fabsf(x1.y) * NL2E);
        const float eg = exp2f(fabsf(x1.z) * NL2E);
        const float eh = exp2f(fabsf(x1.w) * NL2E);

        float pr = 1.0f + ea;                       // prod8 (1+e) in (1,256]
        pr = fmaf(pr, eb, pr);
        pr = fmaf(pr, ec, pr);
        pr = fmaf(pr, ed, pr);
        pr = fmaf(pr, ee, pr);
        pr = fmaf(pr, ef, pr);
        pr = fmaf(pr, eg, pr);
        pr = fmaf(pr, eh, pr);
        lacc += __log2f(pr);                        // one LG2 per 8 elements

        acc += fmaxf(x0.x, 0.0f) + fmaxf(x0.y, 0.0f)
             + fmaxf(x0.z, 0.0f) + fmaxf(x0.w, 0.0f)
             + fmaxf(x1.x, 0.0f) + fmaxf(x1.y, 0.0f)
             + fmaxf(x1.z, 0.0f) + fmaxf(x1.w, 0.0f);

        xs0.x += x0.x; xs0.y += x0.y; xs0.z += x0.z; xs0.w += x0.w;
        xs1.x += x1.x; xs1.y += x1.y; xs1.z += x1.z; xs1.w += x1.w;

        x0 = n0; x1 = n1;
    }

    // Target loaded once per pixel, after the mainloop.
    const float4 t0 = __ldg(target + ((size_t)b * TGT_CH + 0) * HW4 + pix);
    const float4 t1 = __ldg(target + ((size_t)b * TGT_CH + 1) * HW4 + pix);

    acc = fmaf(-t0.x, xs0.x, acc);
    acc = fmaf(-t0.y, xs0.y, acc);
    acc = fmaf(-t0.z, xs0.z, acc);
    acc = fmaf(-t0.w, xs0.w, acc);
    acc = fmaf(-t1.x, xs1.x, acc);
    acc = fmaf(-t1.y, xs1.y, acc);
    acc = fmaf(-t1.z, xs1.z, acc);
    acc = fmaf(-t1.w, xs1.w, acc);
    acc = fmaf(0.693147180559945f, lacc, acc);

    const float v = block_reduce(acc);

    // Last-block-done deterministic finalize.
    __shared__ bool s_last;
    if (tid == 0) {
        g_partials[bid] = v;
        __threadfence();
        unsigned int n = atomicAdd(&g_count, 1u);
        s_last = (n == (unsigned int)(NBLOCKS - 1));
    }
    __syncthreads();

    if (s_last) {
        __threadfence();
        float a = 0.0f;
        #pragma unroll
        for (int i = tid; i < NBLOCKS; i += TPB)
            a += g_partials[i];
        const float total = block_reduce(a);
        if (tid == 0) {
            out[0] = total * (1.0f / 9.0f);   // / NUM_OBJ_CLS
            g_count = 0;                      // reset for graph replays
        }
    }
}

extern "C" void kernel_launch(void* const* d_in, const int* in_sizes, int n_in,
                              void* d_out, int out_size) {
    (void)in_sizes; (void)n_in; (void)out_size;
    const float4* pred   = (const float4*)d_in[0];
    const float4* target = (const float4*)d_in[1];
    float* out = (float*)d_out;

    rpn_bce_fused<<<NBLOCKS, TPB>>>(pred, target, out);
}